// round 15
// baseline (speedup 1.0000x reference)
#include <cuda_runtime.h>
#include <cuda_bf16.h>
#include <cstdint>

#define HW 4096
#define CHN 512

// dynamic smem byte offsets
#define OFF_A  0          // 2 bufs x 32768 : per buf {g0 hi 8K, g0 lo 8K, g1 hi, g1 lo}, [fi][p] bf16 swizzled
#define OFF_B  65536      // 3 bufs x 32768 : per buf {g0 hi, g0 lo, g1 hi, g1 lo}, [f][fi] bf16 swizzled
#define SMEM_TOTAL 163840

#define SWZ_ROW(r) (((uint32_t)(r) & 7u) << 4)

// pre-split, pre-swizzled weights: per group 2048 u32 (hi image) + 2048 u32 (lo image)
__device__ __align__(16) unsigned g_bw[8 * 4096];

__global__ void prep_kernel(const float* __restrict__ w) {
    int idx = blockIdx.x * 256 + threadIdx.x;     // 0..16383, one fi-pair each
    int g   = idx >> 11;
    int f   = (idx >> 5) & 63;
    int fi2 = idx & 31;                           // fi = 2*fi2
    const float* src = w + ((size_t)(g * 64 + f) * 64 + fi2 * 2);
    float v0 = src[0], v1 = src[1];
    uint32_t hw_, lw_;
    asm("cvt.rn.bf16x2.f32 %0, %1, %2;" : "=r"(hw_) : "f"(v1), "f"(v0));
    float h0 = __uint_as_float(hw_ << 16);
    float h1 = __uint_as_float(hw_ & 0xffff0000u);
    float l0 = v0 - h0, l1 = v1 - h1;
    asm("cvt.rn.bf16x2.f32 %0, %1, %2;" : "=r"(lw_) : "f"(l1), "f"(l0));
    uint32_t o  = (uint32_t)(f * 128 + fi2 * 4);
    uint32_t wi = (o ^ SWZ_ROW(f)) >> 2;
    g_bw[g * 4096 + wi]        = hw_;
    g_bw[g * 4096 + 2048 + wi] = lw_;
}

__device__ __forceinline__ void cp16(uint32_t dst, const void* src) {
    asm volatile("cp.async.cg.shared.global [%0], [%1], 16;\n" :: "r"(dst), "l"(src));
}
__device__ __forceinline__ void cp_commit() { asm volatile("cp.async.commit_group;\n"); }

#define LDSM4(r, addr) asm volatile( \
    "ldmatrix.sync.aligned.m8n8.x4.shared.b16 {%0,%1,%2,%3}, [%4];\n" \
    : "=r"((r)[0]), "=r"((r)[1]), "=r"((r)[2]), "=r"((r)[3]) : "r"(addr))

#define LDSM4T(r, addr) asm volatile( \
    "ldmatrix.sync.aligned.m8n8.x4.trans.shared.b16 {%0,%1,%2,%3}, [%4];\n" \
    : "=r"((r)[0]), "=r"((r)[1]), "=r"((r)[2]), "=r"((r)[3]) : "r"(addr))

#define MMA(d, a, b) asm volatile( \
    "mma.sync.aligned.m16n8k16.row.col.f32.bf16.bf16.f32 " \
    "{%0,%1,%2,%3}, {%4,%5,%6,%7}, {%8,%9}, {%0,%1,%2,%3};\n" \
    : "+f"((d)[0]), "+f"((d)[1]), "+f"((d)[2]), "+f"((d)[3]) \
    : "r"((a)[0]), "r"((a)[1]), "r"((a)[2]), "r"((a)[3]), "r"((b)[0]), "r"((b)[1]))

__device__ __forceinline__ float sigmoidf_(float x) { return 1.0f / (1.0f + __expf(-x)); }

__global__ __launch_bounds__(256, 1)
void routing_kernel(const float* __restrict__ x,
                    const float* __restrict__ bias,
                    float* __restrict__ out) {
    extern __shared__ char smem[];
    const uint32_t sb = (uint32_t)__cvta_generic_to_shared(smem);
    const int tid  = threadIdx.x;
    const int lane = tid & 31;
    const int wid  = tid >> 5;
    const int warp_m = wid >> 1;          // position quad: rows [warp_m*16, +16)
    const int warp_n = wid & 1;           // f half: [warp_n*32, +32)
    const int b   = blockIdx.x >> 6;
    const int hw0 = (blockIdx.x & 63) * 64;
    const float* xb = x + (size_t)b * CHN * HW + hw0;

    // ---------- staging ----------
    float4 xr[8];                          // one stage (2 groups) of x, in regs
    auto ldg_x = [&](int s) {
        #pragma unroll
        for (int c = 0; c < 8; c++) {
            int ch = tid + 256 * c;                 // 0..2047 float4 chunks
            int fi = ch >> 4, p4 = (ch & 15) * 4;
            xr[c] = *(const float4*)(xb + (size_t)(s * 128 + fi) * HW + p4);
        }
    };
    auto load_b = [&](int s, int buf) {            // 32KB pre-split B images
        const unsigned* src = g_bw + s * 8192;
        #pragma unroll
        for (int c = 0; c < 8; c++) {
            int ch = tid + 256 * c;
            cp16(sb + (uint32_t)(OFF_B + buf * 32768 + ch * 16), src + ch * 4);
        }
    };
    // regs -> bf16 hi/lo -> swizzled A images, [fi][p] layout
    auto cvt_store = [&](int buf) {
        char* Ab = smem + OFF_A + buf * 32768;
        #pragma unroll
        for (int c = 0; c < 8; c++) {
            int ch = tid + 256 * c;
            int fi128 = ch >> 4;
            int p4 = (ch & 15) * 4;
            float4 v = xr[c];
            uint32_t h01, h23, l01, l23;
            asm("cvt.rn.bf16x2.f32 %0, %1, %2;" : "=r"(h01) : "f"(v.y), "f"(v.x));
            asm("cvt.rn.bf16x2.f32 %0, %1, %2;" : "=r"(h23) : "f"(v.w), "f"(v.z));
            float l0 = v.x - __uint_as_float(h01 << 16);
            float l1 = v.y - __uint_as_float(h01 & 0xffff0000u);
            float l2 = v.z - __uint_as_float(h23 << 16);
            float l3 = v.w - __uint_as_float(h23 & 0xffff0000u);
            asm("cvt.rn.bf16x2.f32 %0, %1, %2;" : "=r"(l01) : "f"(l1), "f"(l0));
            asm("cvt.rn.bf16x2.f32 %0, %1, %2;" : "=r"(l23) : "f"(l3), "f"(l2));
            int g  = fi128 >> 6;
            int fi = fi128 & 63;
            uint32_t off = ((uint32_t)(fi * 128 + p4 * 2)) ^ SWZ_ROW(fi);
            char* base = Ab + g * 16384 + off;
            *(uint2*)base          = make_uint2(h01, h23);
            *(uint2*)(base + 8192) = make_uint2(l01, l23);
        }
    };

    // ---------- per-lane ldmatrix address components ----------
    const int q  = lane >> 3;
    const int r8 = lane & 7;
    // A via ldmatrix.trans from [fi][p]: lane addresses source row fi, col = m block
    const uint32_t a_kq  = (uint32_t)((q >> 1) * 8 + r8);            // fi within k16 block
    const uint32_t a_off = a_kq * 128 +
        (((uint32_t)(warp_m * 32 + (q & 1) * 16)) ^ SWZ_ROW(a_kq));  // + kk*2048 per step
    // B: non-trans from [f][fi]
    const uint32_t b_sw   = SWZ_ROW(r8);
    const uint32_t b_colq = (uint32_t)((q & 1) * 16);
    uint32_t b_rt[2];
    #pragma unroll
    for (int u = 0; u < 2; u++)
        b_rt[u] = (uint32_t)((warp_n * 32 + (2 * u + (q >> 1)) * 8 + r8) * 128);

    float con[8][4][4];
    #pragma unroll
    for (int g = 0; g < 8; g++)
        #pragma unroll
        for (int nt = 0; nt < 4; nt++)
            #pragma unroll
            for (int k = 0; k < 4; k++) con[g][nt][k] = 0.0f;

    // ---------- prologue ----------
    ldg_x(0);
    load_b(0, 0); cp_commit();
    load_b(1, 1); cp_commit();
    cvt_store(0);                                   // consumes xr(0)
    ldg_x(1);
    asm volatile("cp.async.wait_group 1;\n");       // B(0) landed
    __syncthreads();

    // ---------- pipelined stage loop (4 stages x 2 groups), ONE sync/stage ----------
    #pragma unroll
    for (int s = 0; s < 4; s++) {
        const uint32_t Abuf = sb + OFF_A + (s & 1) * 32768;
        const uint32_t Bbuf = sb + OFF_B + (s % 3) * 32768;
        #pragma unroll
        for (int gg = 0; gg < 2; gg++) {
            const int g = 2 * s + gg;
            const uint32_t Ah = Abuf + gg * 16384, Al = Ah + 8192;
            const uint32_t Bh = Bbuf + gg * 16384, Bl = Bh + 8192;
            #pragma unroll
            for (int kk = 0; kk < 4; kk++) {
                uint32_t ah[4], al[4], bh[8], bl[8];
                LDSM4T(ah, Ah + a_off + kk * 2048);
                LDSM4T(al, Al + a_off + kk * 2048);
                uint32_t bcol = ((uint32_t)(kk * 32) + b_colq) ^ b_sw;
                LDSM4(&bh[0], Bh + b_rt[0] + bcol);
                LDSM4(&bh[4], Bh + b_rt[1] + bcol);
                LDSM4(&bl[0], Bl + b_rt[0] + bcol);
                LDSM4(&bl[4], Bl + b_rt[1] + bcol);
                #pragma unroll
                for (int nt = 0; nt < 4; nt++) {
                    MMA(con[g][nt], ah, &bh[nt * 2]);
                    MMA(con[g][nt], ah, &bl[nt * 2]);
                    MMA(con[g][nt], al, &bh[nt * 2]);
                }
            }
        }
        if (s < 3) {
            cvt_store((s + 1) & 1);                 // A[(s+1)&1]: last read mma(s-1), safe
            if (s < 2) {
                ldg_x(s + 2);                       // 2-stage LDG prefetch
                load_b(s + 2, (s + 2) % 3);         // triple-buffered: untouched this stage
                cp_commit();
                asm volatile("cp.async.wait_group 1;\n");   // B(s+1) landed
            } else {
                asm volatile("cp.async.wait_group 0;\n");   // B(3) landed
            }
            __syncthreads();
        }
    }

    // ================= routing epilogue =================
    float* sbuf = (float*)smem;                       // A buf0 region (dead)
    float* abuf = (float*)(smem + 2 * 64 * 36 * 4);   // [64][9]
    const int r0 = warp_m * 16 + (lane >> 2);         // thread's first row (position)

    // Gram matrix S[g][g'] per row, partial over this warp's 8 f-cols
    #pragma unroll
    for (int rr = 0; rr < 2; rr++) {
        float S[36];
        int idx = 0;
        #pragma unroll
        for (int a = 0; a < 8; a++) {
            #pragma unroll
            for (int c = a; c < 8; c++, idx++) {
                float acc = 0.0f;
                #pragma unroll
                for (int nt = 0; nt < 4; nt++) {
                    acc = fmaf(con[a][nt][2 * rr],     con[c][nt][2 * rr],     acc);
                    acc = fmaf(con[a][nt][2 * rr + 1], con[c][nt][2 * rr + 1], acc);
                }
                S[idx] = acc;
            }
        }
        #pragma unroll
        for (int i = 0; i < 36; i++) {
            S[i] += __shfl_xor_sync(0xffffffffu, S[i], 1);
            S[i] += __shfl_xor_sync(0xffffffffu, S[i], 2);
        }
        int row = r0 + rr * 8;
        for (int i = (lane & 3); i < 36; i += 4)
            sbuf[(warp_n * 64 + row) * 36 + i] = S[i];
    }
    __syncthreads();

    // per-position recurrence (threads 0..63)
    if (tid < 64) {
        float Sf[36];
        #pragma unroll
        for (int i = 0; i < 36; i++)
            Sf[i] = sbuf[tid * 36 + i] + sbuf[(64 + tid) * 36 + i];
        auto SM = [&](int a, int c) -> float {
            int lo = a < c ? a : c, hi = a < c ? c : a;
            return Sf[lo * 8 - (lo * (lo + 1)) / 2 + hi];
        };
        float beta[8];
        #pragma unroll
        for (int g = 0; g < 8; g++) {          // iter 0: alpha = 0.5
            float rs = 0.0f;
            #pragma unroll
            for (int gp = 0; gp < 8; gp++) rs += SM(g, gp);
            beta[g] = 0.5f * rs;
        }
        float alpha[8];
        #pragma unroll
        for (int g = 0; g < 8; g++) alpha[g] = sigmoidf_(beta[g]);
        #pragma unroll
        for (int g = 0; g < 8; g++) {          // iter 1
            float acc = 0.0f;
            #pragma unroll
            for (int gp = 0; gp < 8; gp++) acc = fmaf(alpha[gp], SM(gp, g), acc);
            beta[g] += acc;
        }
        #pragma unroll
        for (int g = 0; g < 8; g++) abuf[tid * 9 + g] = sigmoidf_(beta[g]);
    }
    __syncthreads();

    // v = sum_g alpha_g * con_g
    float a0[8], a1[8];
    #pragma unroll
    for (int g = 0; g < 8; g++) {
        a0[g] = abuf[r0 * 9 + g];
        a1[g] = abuf[(r0 + 8) * 9 + g];
    }
    float v[4][4];
    #pragma unroll
    for (int nt = 0; nt < 4; nt++)
        #pragma unroll
        for (int k = 0; k < 4; k++) v[nt][k] = 0.0f;
    #pragma unroll
    for (int g = 0; g < 8; g++)
        #pragma unroll
        for (int nt = 0; nt < 4; nt++) {
            v[nt][0] = fmaf(a0[g], con[g][nt][0], v[nt][0]);
            v[nt][1] = fmaf(a0[g], con[g][nt][1], v[nt][1]);
            v[nt][2] = fmaf(a1[g], con[g][nt][2], v[nt][2]);
            v[nt][3] = fmaf(a1[g], con[g][nt][3], v[nt][3]);
        }

    // transpose through smem; stride 68 floats -> 16B-aligned rows for float4 IO
    float* vbuf = (float*)(smem + 32768);             // A buf1 region (dead by now)
    const int cb = 2 * (lane & 3);
    #pragma unroll
    for (int nt = 0; nt < 4; nt++) {
        int f = warp_n * 32 + nt * 8 + cb;
        vbuf[f * 68 + r0]           = v[nt][0];
        vbuf[(f + 1) * 68 + r0]     = v[nt][1];
        vbuf[f * 68 + r0 + 8]       = v[nt][2];
        vbuf[(f + 1) * 68 + r0 + 8] = v[nt][3];
    }
    __syncthreads();

    float* ob = out + (size_t)b * 64 * HW + hw0;
    #pragma unroll
    for (int c = 0; c < 4; c++) {
        int ch = tid + 256 * c;                       // 0..1023 float4 chunks
        int f = ch >> 4, p4 = (ch & 15) * 4;
        float4 vv = *(const float4*)(vbuf + f * 68 + p4);
        float bf = __ldg(&bias[f]);
        vv.x += bf; vv.y += bf; vv.z += bf; vv.w += bf;
        *(float4*)(ob + (size_t)f * HW + p4) = vv;
    }
}

extern "C" void kernel_launch(void* const* d_in, const int* in_sizes, int n_in,
                              void* d_out, int out_size) {
    const float* x    = (const float*)d_in[0];
    const float* w    = (const float*)d_in[1];
    const float* bias = (const float*)d_in[2];
    float* out = (float*)d_out;

    prep_kernel<<<64, 256>>>(w);

    cudaFuncSetAttribute(routing_kernel,
                         cudaFuncAttributeMaxDynamicSharedMemorySize, SMEM_TOTAL);
    routing_kernel<<<1024, 256, SMEM_TOTAL>>>(x, bias, out);
}

// round 16
// speedup vs baseline: 1.0216x; 1.0216x over previous
#include <cuda_runtime.h>
#include <cuda_bf16.h>
#include <cstdint>

#define HW 4096
#define CHN 512

// dynamic smem byte offsets
#define OFF_A  0          // 2 bufs x 32768 : per buf {g0 hi 8K, g0 lo 8K, g1 hi, g1 lo}, [fi][p] bf16 swizzled
#define OFF_B  65536      // 3 bufs x 32768 : per buf {g0 hi, g0 lo, g1 hi, g1 lo}, [f][fi] bf16 swizzled
#define SMEM_TOTAL 163840

#define SWZ_ROW(r) (((uint32_t)(r) & 7u) << 4)

// pre-split, pre-swizzled weights: per group 2048 u32 (hi image) + 2048 u32 (lo image)
__device__ __align__(16) unsigned g_bw[8 * 4096];

__global__ void prep_kernel(const float* __restrict__ w) {
    int idx = blockIdx.x * 256 + threadIdx.x;     // 0..16383, one fi-pair each
    int g   = idx >> 11;
    int f   = (idx >> 5) & 63;
    int fi2 = idx & 31;                           // fi = 2*fi2
    const float* src = w + ((size_t)(g * 64 + f) * 64 + fi2 * 2);
    float v0 = src[0], v1 = src[1];
    uint32_t hw_, lw_;
    asm("cvt.rn.bf16x2.f32 %0, %1, %2;" : "=r"(hw_) : "f"(v1), "f"(v0));
    float h0 = __uint_as_float(hw_ << 16);
    float h1 = __uint_as_float(hw_ & 0xffff0000u);
    float l0 = v0 - h0, l1 = v1 - h1;
    asm("cvt.rn.bf16x2.f32 %0, %1, %2;" : "=r"(lw_) : "f"(l1), "f"(l0));
    uint32_t o  = (uint32_t)(f * 128 + fi2 * 4);
    uint32_t wi = (o ^ SWZ_ROW(f)) >> 2;
    g_bw[g * 4096 + wi]        = hw_;
    g_bw[g * 4096 + 2048 + wi] = lw_;
}

__device__ __forceinline__ void cp16(uint32_t dst, const void* src) {
    asm volatile("cp.async.cg.shared.global [%0], [%1], 16;\n" :: "r"(dst), "l"(src));
}
__device__ __forceinline__ void cp_commit() { asm volatile("cp.async.commit_group;\n"); }

#define LDSM4(r, addr) asm volatile( \
    "ldmatrix.sync.aligned.m8n8.x4.shared.b16 {%0,%1,%2,%3}, [%4];\n" \
    : "=r"((r)[0]), "=r"((r)[1]), "=r"((r)[2]), "=r"((r)[3]) : "r"(addr))

#define LDSM4T(r, addr) asm volatile( \
    "ldmatrix.sync.aligned.m8n8.x4.trans.shared.b16 {%0,%1,%2,%3}, [%4];\n" \
    : "=r"((r)[0]), "=r"((r)[1]), "=r"((r)[2]), "=r"((r)[3]) : "r"(addr))

#define MMA(d, a, b) asm volatile( \
    "mma.sync.aligned.m16n8k16.row.col.f32.bf16.bf16.f32 " \
    "{%0,%1,%2,%3}, {%4,%5,%6,%7}, {%8,%9}, {%0,%1,%2,%3};\n" \
    : "+f"((d)[0]), "+f"((d)[1]), "+f"((d)[2]), "+f"((d)[3]) \
    : "r"((a)[0]), "r"((a)[1]), "r"((a)[2]), "r"((a)[3]), "r"((b)[0]), "r"((b)[1]))

__device__ __forceinline__ float sigmoidf_(float x) { return 1.0f / (1.0f + __expf(-x)); }

__global__ __launch_bounds__(256, 1)
void routing_kernel(const float* __restrict__ x,
                    const float* __restrict__ bias,
                    float* __restrict__ out) {
    extern __shared__ char smem[];
    const uint32_t sb = (uint32_t)__cvta_generic_to_shared(smem);
    const int tid  = threadIdx.x;
    const int lane = tid & 31;
    const int wid  = tid >> 5;
    const int warp_m = wid >> 1;          // position quad: rows [warp_m*16, +16)
    const int warp_n = wid & 1;           // f half: [warp_n*32, +32)
    const int b   = blockIdx.x >> 6;
    const int hw0 = (blockIdx.x & 63) * 64;
    const float* xb = x + (size_t)b * CHN * HW + hw0;

    // ---------- staging ----------
    float4 xr[8];                          // one stage (2 groups) of x, in regs
    auto ldg_x = [&](int s) {
        #pragma unroll
        for (int c = 0; c < 8; c++) {
            int ch = tid + 256 * c;                 // 0..2047 float4 chunks
            int fi = ch >> 4, p4 = (ch & 15) * 4;
            xr[c] = *(const float4*)(xb + (size_t)(s * 128 + fi) * HW + p4);
        }
    };
    auto load_b = [&](int s, int buf) {            // 32KB pre-split B images
        const unsigned* src = g_bw + s * 8192;
        #pragma unroll
        for (int c = 0; c < 8; c++) {
            int ch = tid + 256 * c;
            cp16(sb + (uint32_t)(OFF_B + buf * 32768 + ch * 16), src + ch * 4);
        }
    };
    // regs -> bf16 hi/lo -> swizzled A images, [fi][p] layout
    auto cvt_store = [&](int buf) {
        char* Ab = smem + OFF_A + buf * 32768;
        #pragma unroll
        for (int c = 0; c < 8; c++) {
            int ch = tid + 256 * c;
            int fi128 = ch >> 4;
            int p4 = (ch & 15) * 4;
            float4 v = xr[c];
            uint32_t h01, h23, l01, l23;
            asm("cvt.rn.bf16x2.f32 %0, %1, %2;" : "=r"(h01) : "f"(v.y), "f"(v.x));
            asm("cvt.rn.bf16x2.f32 %0, %1, %2;" : "=r"(h23) : "f"(v.w), "f"(v.z));
            float l0 = v.x - __uint_as_float(h01 << 16);
            float l1 = v.y - __uint_as_float(h01 & 0xffff0000u);
            float l2 = v.z - __uint_as_float(h23 << 16);
            float l3 = v.w - __uint_as_float(h23 & 0xffff0000u);
            asm("cvt.rn.bf16x2.f32 %0, %1, %2;" : "=r"(l01) : "f"(l1), "f"(l0));
            asm("cvt.rn.bf16x2.f32 %0, %1, %2;" : "=r"(l23) : "f"(l3), "f"(l2));
            int g  = fi128 >> 6;
            int fi = fi128 & 63;
            uint32_t off = ((uint32_t)(fi * 128 + p4 * 2)) ^ SWZ_ROW(fi);
            char* base = Ab + g * 16384 + off;
            *(uint2*)base          = make_uint2(h01, h23);
            *(uint2*)(base + 8192) = make_uint2(l01, l23);
        }
    };

    // ---------- per-lane ldmatrix address components ----------
    const int q  = lane >> 3;
    const int r8 = lane & 7;
    // A via ldmatrix.trans from [fi][p]: lane addresses source row fi, col = m block
    const uint32_t a_kq  = (uint32_t)((q >> 1) * 8 + r8);            // fi within k16 block
    const uint32_t a_off = a_kq * 128 +
        (((uint32_t)(warp_m * 32 + (q & 1) * 16)) ^ SWZ_ROW(a_kq));  // + kk*2048 per step
    // B: non-trans from [f][fi]
    const uint32_t b_sw   = SWZ_ROW(r8);
    const uint32_t b_colq = (uint32_t)((q & 1) * 16);
    uint32_t b_rt[2];
    #pragma unroll
    for (int u = 0; u < 2; u++)
        b_rt[u] = (uint32_t)((warp_n * 32 + (2 * u + (q >> 1)) * 8 + r8) * 128);

    float con[8][4][4];
    #pragma unroll
    for (int g = 0; g < 8; g++)
        #pragma unroll
        for (int nt = 0; nt < 4; nt++)
            #pragma unroll
            for (int k = 0; k < 4; k++) con[g][nt][k] = 0.0f;

    // ---------- prologue ----------
    ldg_x(0);
    load_b(0, 0); cp_commit();
    load_b(1, 1); cp_commit();
    cvt_store(0);                                   // consumes xr(0)
    ldg_x(1);
    asm volatile("cp.async.wait_group 1;\n");       // B(0) landed
    __syncthreads();

    // ---------- pipelined stage loop (4 stages x 2 groups), ONE sync/stage ----------
    #pragma unroll
    for (int s = 0; s < 4; s++) {
        const uint32_t Abuf = sb + OFF_A + (s & 1) * 32768;
        const uint32_t Bbuf = sb + OFF_B + (s % 3) * 32768;
        #pragma unroll
        for (int gg = 0; gg < 2; gg++) {
            const int g = 2 * s + gg;
            const uint32_t Ah = Abuf + gg * 16384, Al = Ah + 8192;
            const uint32_t Bh = Bbuf + gg * 16384, Bl = Bh + 8192;
            #pragma unroll
            for (int kk = 0; kk < 4; kk++) {
                uint32_t ah[4], al[4], bh[8], bl[8];
                LDSM4T(ah, Ah + a_off + kk * 2048);
                LDSM4T(al, Al + a_off + kk * 2048);
                uint32_t bcol = ((uint32_t)(kk * 32) + b_colq) ^ b_sw;
                LDSM4(&bh[0], Bh + b_rt[0] + bcol);
                LDSM4(&bh[4], Bh + b_rt[1] + bcol);
                LDSM4(&bl[0], Bl + b_rt[0] + bcol);
                LDSM4(&bl[4], Bl + b_rt[1] + bcol);
                #pragma unroll
                for (int nt = 0; nt < 4; nt++) {
                    MMA(con[g][nt], ah, &bh[nt * 2]);
                    MMA(con[g][nt], ah, &bl[nt * 2]);
                    MMA(con[g][nt], al, &bh[nt * 2]);
                }
            }
        }
        if (s < 3) {
            cvt_store((s + 1) & 1);                 // A[(s+1)&1]: last read mma(s-1), safe
            if (s < 2) {
                ldg_x(s + 2);                       // 2-stage LDG prefetch
                load_b(s + 2, (s + 2) % 3);         // triple-buffered: untouched this stage
                cp_commit();
                asm volatile("cp.async.wait_group 1;\n");   // B(s+1) landed
            } else {
                asm volatile("cp.async.wait_group 0;\n");   // B(3) landed
            }
            __syncthreads();
        }
    }

    // ================= routing epilogue =================
    float* sbuf = (float*)smem;                       // A buf0 region (dead)
    float* abuf = (float*)(smem + 2 * 64 * 36 * 4);   // [64][9]
    const int r0 = warp_m * 16 + (lane >> 2);         // thread's first row (position)

    // Gram matrix S[g][g'] per row, partial over this warp's 8 f-cols
    #pragma unroll
    for (int rr = 0; rr < 2; rr++) {
        float S[36];
        int idx = 0;
        #pragma unroll
        for (int a = 0; a < 8; a++) {
            #pragma unroll
            for (int c = a; c < 8; c++, idx++) {
                float acc = 0.0f;
                #pragma unroll
                for (int nt = 0; nt < 4; nt++) {
                    acc = fmaf(con[a][nt][2 * rr],     con[c][nt][2 * rr],     acc);
                    acc = fmaf(con[a][nt][2 * rr + 1], con[c][nt][2 * rr + 1], acc);
                }
                S[idx] = acc;
            }
        }
        #pragma unroll
        for (int i = 0; i < 36; i++) {
            S[i] += __shfl_xor_sync(0xffffffffu, S[i], 1);
            S[i] += __shfl_xor_sync(0xffffffffu, S[i], 2);
        }
        int row = r0 + rr * 8;
        for (int i = (lane & 3); i < 36; i += 4)
            sbuf[(warp_n * 64 + row) * 36 + i] = S[i];
    }
    __syncthreads();

    // per-position recurrence (threads 0..63)
    if (tid < 64) {
        float Sf[36];
        #pragma unroll
        for (int i = 0; i < 36; i++)
            Sf[i] = sbuf[tid * 36 + i] + sbuf[(64 + tid) * 36 + i];
        auto SM = [&](int a, int c) -> float {
            int lo = a < c ? a : c, hi = a < c ? c : a;
            return Sf[lo * 8 - (lo * (lo + 1)) / 2 + hi];
        };
        float beta[8];
        #pragma unroll
        for (int g = 0; g < 8; g++) {          // iter 0: alpha = 0.5
            float rs = 0.0f;
            #pragma unroll
            for (int gp = 0; gp < 8; gp++) rs += SM(g, gp);
            beta[g] = 0.5f * rs;
        }
        float alpha[8];
        #pragma unroll
        for (int g = 0; g < 8; g++) alpha[g] = sigmoidf_(beta[g]);
        #pragma unroll
        for (int g = 0; g < 8; g++) {          // iter 1
            float acc = 0.0f;
            #pragma unroll
            for (int gp = 0; gp < 8; gp++) acc = fmaf(alpha[gp], SM(gp, g), acc);
            beta[g] += acc;
        }
        #pragma unroll
        for (int g = 0; g < 8; g++) abuf[tid * 9 + g] = sigmoidf_(beta[g]);
    }
    __syncthreads();

    // v = sum_g alpha_g * con_g
    float a0[8], a1[8];
    #pragma unroll
    for (int g = 0; g < 8; g++) {
        a0[g] = abuf[r0 * 9 + g];
        a1[g] = abuf[(r0 + 8) * 9 + g];
    }
    float v[4][4];
    #pragma unroll
    for (int nt = 0; nt < 4; nt++)
        #pragma unroll
        for (int k = 0; k < 4; k++) v[nt][k] = 0.0f;
    #pragma unroll
    for (int g = 0; g < 8; g++)
        #pragma unroll
        for (int nt = 0; nt < 4; nt++) {
            v[nt][0] = fmaf(a0[g], con[g][nt][0], v[nt][0]);
            v[nt][1] = fmaf(a0[g], con[g][nt][1], v[nt][1]);
            v[nt][2] = fmaf(a1[g], con[g][nt][2], v[nt][2]);
            v[nt][3] = fmaf(a1[g], con[g][nt][3], v[nt][3]);
        }

    // transpose through smem; stride 68 floats -> 16B-aligned rows for float4 IO
    float* vbuf = (float*)(smem + 32768);             // A buf1 region (dead by now)
    const int cb = 2 * (lane & 3);
    #pragma unroll
    for (int nt = 0; nt < 4; nt++) {
        int f = warp_n * 32 + nt * 8 + cb;
        vbuf[f * 68 + r0]           = v[nt][0];
        vbuf[(f + 1) * 68 + r0]     = v[nt][1];
        vbuf[f * 68 + r0 + 8]       = v[nt][2];
        vbuf[(f + 1) * 68 + r0 + 8] = v[nt][3];
    }
    __syncthreads();

    float* ob = out + (size_t)b * 64 * HW + hw0;
    #pragma unroll
    for (int c = 0; c < 4; c++) {
        int ch = tid + 256 * c;                       // 0..1023 float4 chunks
        int f = ch >> 4, p4 = (ch & 15) * 4;
        float4 vv = *(const float4*)(vbuf + f * 68 + p4);
        float bf = __ldg(&bias[f]);
        vv.x += bf; vv.y += bf; vv.z += bf; vv.w += bf;
        *(float4*)(ob + (size_t)f * HW + p4) = vv;
    }
}

extern "C" void kernel_launch(void* const* d_in, const int* in_sizes, int n_in,
                              void* d_out, int out_size) {
    const float* x    = (const float*)d_in[0];
    const float* w    = (const float*)d_in[1];
    const float* bias = (const float*)d_in[2];
    float* out = (float*)d_out;

    prep_kernel<<<64, 256>>>(w);

    cudaFuncSetAttribute(routing_kernel,
                         cudaFuncAttributeMaxDynamicSharedMemorySize, SMEM_TOTAL);
    routing_kernel<<<1024, 256, SMEM_TOTAL>>>(x, bias, out);
}